// round 13
// baseline (speedup 1.0000x reference)
#include <cuda_runtime.h>
#include <cuda_bf16.h>
#include <cstdint>
#include <math.h>

#define BB   64
#define SS   512
#define HID  1024
#define G4   4096
#define ROWS (BB*SS)
#define NCTA 128

// ---------------- device scratch ----------------
__device__ __nv_bfloat16 g_xh[ROWS*HID];
__device__ __nv_bfloat16 g_xl[ROWS*HID];
__device__ __nv_bfloat16 g_wih[(size_t)G4*HID];
__device__ __nv_bfloat16 g_wil[(size_t)G4*HID];
__device__ int8_t g_q1[(size_t)G4*HID];      // Wh digit1 (x2^-11), transposed+interleaved
__device__ int8_t g_q2[(size_t)G4*HID];      // Wh digit2 (x2^-18)
__device__ float g_bias[G4];
__device__ float g_xproj[(size_t)SS*BB*G4];
__device__ int8_t g_h1[2][BB*HID];           // h digit1 (x2^-7)
__device__ int8_t g_h2[2][BB*HID];           // h digit2 (x2^-14)
__device__ int g_flag[NCTA];

// ---------------- helpers ----------------
__device__ __forceinline__ uint32_t cvta_s(const void* p){
    return (uint32_t)__cvta_generic_to_shared(p);
}
__device__ __forceinline__ uint32_t lds32(uint32_t a){
    uint32_t v; asm volatile("ld.shared.b32 %0,[%1];" : "=r"(v) : "r"(a)); return v;
}
__device__ __forceinline__ void cpa16(uint32_t s, const void* g){
    asm volatile("cp.async.cg.shared.global [%0],[%1],16;" :: "r"(s), "l"(g));
}
#define CP_COMMIT() asm volatile("cp.async.commit_group;")
#define CP_WAIT(N)  asm volatile("cp.async.wait_group %0;" :: "n"(N))

#define MMA_BF16(d, a, b) \
    asm volatile("mma.sync.aligned.m16n8k16.row.col.f32.bf16.bf16.f32 " \
                 "{%0,%1,%2,%3},{%4,%5,%6,%7},{%8,%9},{%0,%1,%2,%3};" \
                 : "+f"(d[0]), "+f"(d[1]), "+f"(d[2]), "+f"(d[3]) \
                 : "r"(a[0]), "r"(a[1]), "r"(a[2]), "r"(a[3]), "r"(b[0]), "r"(b[1]))

#define IMMA(d, a, b) \
    asm volatile("mma.sync.aligned.m16n8k32.row.col.s32.s8.s8.s32 " \
                 "{%0,%1,%2,%3},{%4,%5,%6,%7},{%8,%9},{%0,%1,%2,%3};" \
                 : "+r"(d[0]), "+r"(d[1]), "+r"(d[2]), "+r"(d[3]) \
                 : "r"(a[0]), "r"(a[1]), "r"(a[2]), "r"(a[3]), "r"(b[0]), "r"(b[1]))

__device__ __forceinline__ float sigm(float x){ return 1.f/(1.f + __expf(-x)); }

// ---------------- prep ----------------
__global__ void k_split_x(const float* __restrict__ x){
    int i = blockIdx.x*blockDim.x + threadIdx.x;
    int stride = gridDim.x*blockDim.x;
    for (; i < ROWS*HID; i += stride){
        float v = x[i];
        __nv_bfloat16 h = __float2bfloat16(v);
        g_xh[i] = h;
        g_xl[i] = __float2bfloat16(v - __bfloat162float(h));
    }
}

// transposed + gate-interleaved weights (col = 4*j + gate)
__global__ void k_prep_w(const float* Wii, const float* Wfi, const float* Wgi, const float* Woi,
                         const float* Wih, const float* Wfh, const float* Wgh, const float* Woh,
                         const float* bii, const float* bih, const float* bfi, const float* bfh,
                         const float* bgi, const float* bgh, const float* boi, const float* boh){
    size_t idx = (size_t)blockIdx.x*256 + threadIdx.x;
    if (idx >= (size_t)G4*HID) return;
    int c = (int)(idx >> 10), k = (int)(idx & 1023);
    int j = c >> 2, gg = c & 3;
    const float* wi = (gg==0)?Wii:(gg==1)?Wfi:(gg==2)?Wgi:Woi;
    const float* wh = (gg==0)?Wih:(gg==1)?Wfh:(gg==2)?Wgh:Woh;
    float vi = wi[(size_t)k*HID + j];
    float vh = wh[(size_t)k*HID + j];
    __nv_bfloat16 h1 = __float2bfloat16(vi);
    g_wih[idx] = h1; g_wil[idx] = __float2bfloat16(vi - __bfloat162float(h1));
    // int8 digit split of Wh: W = q1*2^-11 + q2*2^-18 + eps(<=2^-19)
    float q1f = rintf(vh * 2048.f);
    q1f = fminf(127.f, fmaxf(-127.f, q1f));
    float r = vh - q1f * (1.f/2048.f);
    float q2f = rintf(r * 262144.f);
    q2f = fminf(127.f, fmaxf(-127.f, q2f));
    g_q1[idx] = (int8_t)q1f;
    g_q2[idx] = (int8_t)q2f;
    if (idx < G4){
        int jj = (int)(idx >> 2); int g2 = (int)(idx & 3);
        const float* b1 = (g2==0)?bii:(g2==1)?bfi:(g2==2)?bgi:boi;
        const float* b2 = (g2==0)?bih:(g2==1)?bfh:(g2==2)?bgh:boh;
        g_bias[idx] = b1[jj] + b2[jj];
    }
}

__global__ void k_init(){
    int i = blockIdx.x*256 + threadIdx.x;
    g_h1[0][i] = 0; g_h1[1][i] = 0;
    g_h2[0][i] = 0; g_h2[1][i] = 0;
    if (i < NCTA) g_flag[i] = 0;
}

// ---------------- xproj GEMM [32768,1024]x[1024,4096], 3-term bf16 (unchanged) ----
#define XP_STAGE 24576
#define RB 48

__global__ void __launch_bounds__(256) k_xproj(){
    extern __shared__ __align__(16) char smem_raw[];
    const uint32_t sbase = cvta_s(smem_raw);
    int tid = threadIdx.x;
    int lane = tid & 31, warp = tid >> 5;
    int g = lane >> 2, tq = lane & 3;
    int wm = warp >> 2, wn = warp & 3;
    int m0 = blockIdx.y * 128, n0 = blockIdx.x * 128;

    auto stage_load = [&](int kt, int s){
        int arr = tid >> 7, rem = tid & 127;
        int chunk = rem & 1, rc = rem >> 1;
        const __nv_bfloat16* gA = arr ? g_xl : g_xh;
        const __nv_bfloat16* gB = arr ? g_wil : g_wih;
        uint32_t aA = sbase + s*XP_STAGE + arr*6144;
        uint32_t aB = sbase + s*XP_STAGE + 12288 + arr*6144;
        #pragma unroll
        for (int i = 0; i < 2; i++){
            int row = rc + i*64;
            cpa16(aA + row*RB + chunk*16, gA + (size_t)(m0+row)*HID + kt*16 + chunk*8);
            cpa16(aB + row*RB + chunk*16, gB + (size_t)(n0+row)*HID + kt*16 + chunk*8);
        }
        CP_COMMIT();
    };

    stage_load(0, 0);
    stage_load(1, 1);

    float acc[4][4][4];
    #pragma unroll
    for (int ma = 0; ma < 4; ma++)
        #pragma unroll
        for (int na = 0; na < 4; na++){
            int c = n0 + wn*32 + na*8 + 2*tq;
            float b0 = g_bias[c], b1 = g_bias[c+1];
            acc[ma][na][0] = b0; acc[ma][na][1] = b1;
            acc[ma][na][2] = b0; acc[ma][na][3] = b1;
        }

    for (int kt = 0; kt < 64; kt++){
        CP_WAIT(1);
        __syncthreads();
        if (kt + 2 < 64) stage_load(kt + 2, (kt + 2) % 3);
        else CP_COMMIT();

        uint32_t st = sbase + (kt % 3)*XP_STAGE;
        uint32_t Ah = st, Al = st + 6144, Bh = st + 12288, Bl = st + 18432;
        uint32_t ah[4][4], al[4][4], bh[4][2], bl[4][2];
        #pragma unroll
        for (int ma = 0; ma < 4; ma++){
            int r = wm*64 + ma*16 + g;
            uint32_t o0 = r*RB + tq*4, o1 = (r+8)*RB + tq*4;
            ah[ma][0] = lds32(Ah + o0);      ah[ma][1] = lds32(Ah + o1);
            ah[ma][2] = lds32(Ah + o0 + 16); ah[ma][3] = lds32(Ah + o1 + 16);
            al[ma][0] = lds32(Al + o0);      al[ma][1] = lds32(Al + o1);
            al[ma][2] = lds32(Al + o0 + 16); al[ma][3] = lds32(Al + o1 + 16);
        }
        #pragma unroll
        for (int na = 0; na < 4; na++){
            int cb = wn*32 + na*8 + g;
            uint32_t o = cb*RB + tq*4;
            bh[na][0] = lds32(Bh + o); bh[na][1] = lds32(Bh + o + 16);
            bl[na][0] = lds32(Bl + o); bl[na][1] = lds32(Bl + o + 16);
        }
        #pragma unroll
        for (int ma = 0; ma < 4; ma++)
            #pragma unroll
            for (int na = 0; na < 4; na++){
                MMA_BF16(acc[ma][na], ah[ma], bh[na]);
                MMA_BF16(acc[ma][na], ah[ma], bl[na]);
                MMA_BF16(acc[ma][na], al[ma], bh[na]);
            }
    }

    CP_WAIT(0);
    __syncthreads();
    float* sOut = (float*)smem_raw;  // 128 x 132
    #pragma unroll
    for (int ma = 0; ma < 4; ma++)
        #pragma unroll
        for (int na = 0; na < 4; na++){
            int r = wm*64 + ma*16 + g;
            int c = wn*32 + na*8 + 2*tq;
            sOut[r*132 + c]       = acc[ma][na][0];
            sOut[r*132 + c + 1]   = acc[ma][na][1];
            sOut[(r+8)*132 + c]   = acc[ma][na][2];
            sOut[(r+8)*132 + c+1] = acc[ma][na][3];
        }
    __syncthreads();
    #pragma unroll
    for (int it = 0; it < 16; it++){
        int r2 = (tid >> 5) + it*8;
        int rg = m0 + r2;
        int b = rg >> 9, s = rg & 511;
        float4 v = *(float4*)(sOut + r2*132 + lane*4);
        *(float4*)(g_xproj + ((size_t)(s*64 + b))*G4 + n0 + lane*4) = v;
    }
}

// ---------------- persistent int8 IMMA recurrence ----------------
// gate = xproj + 2^-18 * sum(H1*W1) + 2^-25 * sum(H1*W2 + H2*W1)
// SMEM map (bytes), row pitch 80 (conflict-free: bank stride 20):
//   [0, 40960)        B1 resident: 16 chunks x 32 rows x 80
//   [40960, 81920)    B2 resident
//   [81920, 122880)   A stages: 4 x 10240 (128 rows x 80; rows 0-63 H1, 64-127 H2)
//   [122880, 132096)  sG gate buffer: 64 x 36 floats
#define RQ_B1   0u
#define RQ_B2   40960u
#define RQ_A    81920u
#define RQ_SG   122880u
#define RQ_SMEM 132096

__global__ void __launch_bounds__(256, 1) k_recur(float* __restrict__ out){
    extern __shared__ __align__(16) char smem_raw[];
    const uint32_t sbase = cvta_s(smem_raw);
    float* sG = (float*)(smem_raw + RQ_SG);
    int tid = threadIdx.x;
    int lane = tid & 31, warp = tid >> 5;
    int g = lane >> 2, tq = lane & 3;
    int wm = warp & 3, wn = warp >> 2;       // 4 m-tiles x 2 n-halves
    int n0 = blockIdx.x * 32;
    const float S1 = 1.f/262144.f;           // 2^-18
    const float S2 = 1.f/33554432.f;         // 2^-25

    // ---- resident Wh digit slices (once): 2 digits x 16 chunks x 32 rows x 4 ----
    for (int i = tid; i < 4096; i += 256){
        int d = i >> 11, j = i & 2047;
        int ch = j >> 7, r = (j >> 2) & 31, c16 = j & 3;
        uint32_t dst = sbase + (d ? RQ_B2 : RQ_B1)
                     + (uint32_t)ch*2560u + (uint32_t)r*80u + (uint32_t)c16*16u;
        const int8_t* src = (d ? g_q2 : g_q1)
            + (size_t)(n0 + r)*HID + ch*64 + c16*16;
        cpa16(dst, src);
    }
    CP_COMMIT();

    float cst[2] = {0.f, 0.f};

    for (int t = 0; t < SS; t++){
        const int8_t* h1in = g_h1[t & 1];
        const int8_t* h2in = g_h2[t & 1];

        auto load_chunk = [&](int c){
            #pragma unroll
            for (int rep = 0; rep < 2; rep++){
                int j = tid + rep*256;           // 0..511
                int R = j >> 2, c16 = j & 3;
                uint32_t dst = sbase + RQ_A + (uint32_t)(c & 3)*10240u
                             + (uint32_t)R*80u + (uint32_t)c16*16u;
                const int8_t* src = (R < 64 ? h1in + (size_t)R*HID
                                            : h2in + (size_t)(R - 64)*HID)
                                    + c*64 + c16*16;
                cpa16(dst, src);
            }
            CP_COMMIT();
        };

        load_chunk(0); load_chunk(1); load_chunk(2);

        // prefetch this step's xproj slice (independent of h)
        float4 xv[2];
        #pragma unroll
        for (int p = 0; p < 2; p++){
            int b = p*32 + (tid >> 3), jl = tid & 7;
            xv[p] = *(const float4*)(g_xproj + ((size_t)t*BB + b)*G4 + n0 + jl*4);
        }

        int accH[2][4], accL[2][4];
        #pragma unroll
        for (int nf = 0; nf < 2; nf++)
            #pragma unroll
            for (int k = 0; k < 4; k++){ accH[nf][k] = 0; accL[nf][k] = 0; }

        for (int c = 0; c < 16; c++){
            CP_WAIT(2);
            __syncthreads();
            if (c + 3 < 16) load_chunk(c + 3);
            else CP_COMMIT();

            uint32_t Ab = sbase + RQ_A + (uint32_t)(c & 3)*10240u;
            uint32_t Bb1 = sbase + RQ_B1 + (uint32_t)c*2560u;
            uint32_t Bb2 = sbase + RQ_B2 + (uint32_t)c*2560u;
            #pragma unroll
            for (int s = 0; s < 2; s++){
                uint32_t kb = (uint32_t)s*32u;
                uint32_t a1[4], a2[4];
                {
                    uint32_t o0 = (uint32_t)(wm*16 + g)*80u + kb + tq*4;
                    uint32_t o1 = o0 + 8*80u;
                    a1[0] = lds32(Ab + o0);      a1[1] = lds32(Ab + o1);
                    a1[2] = lds32(Ab + o0 + 16); a1[3] = lds32(Ab + o1 + 16);
                    a2[0] = lds32(Ab + o0 + 64*80u);      a2[1] = lds32(Ab + o1 + 64*80u);
                    a2[2] = lds32(Ab + o0 + 64*80u + 16); a2[3] = lds32(Ab + o1 + 64*80u + 16);
                }
                #pragma unroll
                for (int nf = 0; nf < 2; nf++){
                    uint32_t o = (uint32_t)(wn*16 + nf*8 + g)*80u + kb + tq*4;
                    uint32_t b1[2], b2[2];
                    b1[0] = lds32(Bb1 + o); b1[1] = lds32(Bb1 + o + 16);
                    b2[0] = lds32(Bb2 + o); b2[1] = lds32(Bb2 + o + 16);
                    IMMA(accH[nf], a1, b1);
                    IMMA(accL[nf], a1, b2);
                    IMMA(accL[nf], a2, b1);
                }
            }
        }

        // ---- epilogue: combine scales, dump to sG ----
        #pragma unroll
        for (int nf = 0; nf < 2; nf++){
            int r = wm*16 + g;
            int cc = wn*16 + nf*8 + 2*tq;
            sG[r*36 + cc]       = (float)accH[nf][0]*S1 + (float)accL[nf][0]*S2;
            sG[r*36 + cc + 1]   = (float)accH[nf][1]*S1 + (float)accL[nf][1]*S2;
            sG[(r+8)*36 + cc]   = (float)accH[nf][2]*S1 + (float)accL[nf][2]*S2;
            sG[(r+8)*36 + cc+1] = (float)accH[nf][3]*S1 + (float)accL[nf][3]*S2;
        }
        __syncthreads();

        bool last = (t == SS - 1);
        int8_t* h1out = g_h1[(t + 1) & 1];
        int8_t* h2out = g_h2[(t + 1) & 1];
        #pragma unroll
        for (int p = 0; p < 2; p++){
            int b = p*32 + (tid >> 3), jl = tid & 7;
            float4 gt = *(float4*)(sG + b*36 + jl*4);
            float iv = sigm(gt.x + xv[p].x);
            float fv = sigm(gt.y + xv[p].y);
            float gv = tanhf(gt.z + xv[p].z);
            float ov = sigm(gt.w + xv[p].w);
            float cn = fv*cst[p] + iv*gv;
            cst[p] = cn;
            float h = ov*tanhf(cn);
            int ci = b*HID + (n0 >> 2) + jl;
            float f1 = rintf(h * 128.f);
            f1 = fminf(127.f, fmaxf(-127.f, f1));
            float r = h - f1 * 0.0078125f;
            float f2 = rintf(r * 16384.f);
            f2 = fminf(127.f, fmaxf(-127.f, f2));
            h1out[ci] = (int8_t)f1;
            h2out[ci] = (int8_t)f2;
            if (last){ out[ci] = h; out[BB*HID + ci] = cn; }
        }
        __syncthreads();

        // ---- distributed grid barrier ----
        if (tid == 0){
            __threadfence();
            asm volatile("st.global.release.gpu.s32 [%0], %1;"
                         :: "l"(g_flag + blockIdx.x), "r"(t + 1) : "memory");
        }
        if (tid < NCTA){
            int v;
            do {
                asm volatile("ld.global.acquire.gpu.s32 %0, [%1];"
                             : "=r"(v) : "l"(g_flag + tid));
            } while (v < t + 1);
        }
        __syncthreads();
    }
}

// ---------------- launch ----------------
extern "C" void kernel_launch(void* const* d_in, const int* in_sizes, int n_in,
                              void* d_out, int out_size){
    // dict order: x, Wii,Wfi,Wgi,Woi, Wih,Wfh,Wgh,Woh, bii,bih,bfi,bfh,bgi,bgh,boi,boh
    const float* x = nullptr;
    const float* w[8] = {nullptr}; const float* bp[8] = {nullptr};
    int nw = 0, nb = 0;
    for (int i = 0; i < n_in; i++){
        if (in_sizes[i] == ROWS*HID)      x = (const float*)d_in[i];
        else if (in_sizes[i] == HID*HID){ if (nw < 8) w[nw++] = (const float*)d_in[i]; }
        else if (in_sizes[i] == HID){     if (nb < 8) bp[nb++] = (const float*)d_in[i]; }
    }
    float* out = (float*)d_out;

    cudaFuncSetAttribute(k_xproj, cudaFuncAttributeMaxDynamicSharedMemorySize, 3*XP_STAGE);
    cudaFuncSetAttribute(k_recur, cudaFuncAttributeMaxDynamicSharedMemorySize, RQ_SMEM);

    k_split_x<<<2048, 256>>>(x);
    k_prep_w<<<16384, 256>>>(w[0], w[1], w[2], w[3], w[4], w[5], w[6], w[7],
                             bp[0], bp[1], bp[2], bp[3], bp[4], bp[5], bp[6], bp[7]);
    k_init<<<256, 256>>>();
    dim3 gx(32, 256);
    k_xproj<<<gx, 256, 3*XP_STAGE>>>();
    k_recur<<<NCTA, 256, RQ_SMEM>>>(out);
}

// round 15
// speedup vs baseline: 1.5756x; 1.5756x over previous
#include <cuda_runtime.h>
#include <cuda_bf16.h>
#include <cuda_fp16.h>
#include <cstdint>
#include <math.h>

#define BB   64
#define SS   512
#define HID  1024
#define G4   4096
#define ROWS (BB*SS)
#define NCTA 128

// ---------------- device scratch ----------------
__device__ __nv_bfloat16 g_xh[ROWS*HID];
__device__ __nv_bfloat16 g_xl[ROWS*HID];
__device__ __nv_bfloat16 g_wih[(size_t)G4*HID];
__device__ __nv_bfloat16 g_wil[(size_t)G4*HID];
__device__ __half g_p1[(size_t)G4*HID];      // Wh fp16 digit1, transposed+interleaved
__device__ __half g_p2[(size_t)G4*HID];      // Wh fp16 digit2 (residual)
__device__ float g_bias[G4];
__device__ float g_xproj[(size_t)SS*BB*G4];
__device__ __half g_hf[2][BB*HID];           // h as single fp16, ping-pong
__device__ int g_flag[NCTA];

// ---------------- helpers ----------------
__device__ __forceinline__ uint32_t cvta_s(const void* p){
    return (uint32_t)__cvta_generic_to_shared(p);
}
__device__ __forceinline__ uint32_t lds32(uint32_t a){
    uint32_t v; asm volatile("ld.shared.b32 %0,[%1];" : "=r"(v) : "r"(a)); return v;
}
__device__ __forceinline__ void cpa16(uint32_t s, const void* g){
    asm volatile("cp.async.cg.shared.global [%0],[%1],16;" :: "r"(s), "l"(g));
}
#define CP_COMMIT() asm volatile("cp.async.commit_group;")
#define CP_WAIT(N)  asm volatile("cp.async.wait_group %0;" :: "n"(N))

#define MMA_BF16(d, a, b) \
    asm volatile("mma.sync.aligned.m16n8k16.row.col.f32.bf16.bf16.f32 " \
                 "{%0,%1,%2,%3},{%4,%5,%6,%7},{%8,%9},{%0,%1,%2,%3};" \
                 : "+f"(d[0]), "+f"(d[1]), "+f"(d[2]), "+f"(d[3]) \
                 : "r"(a[0]), "r"(a[1]), "r"(a[2]), "r"(a[3]), "r"(b[0]), "r"(b[1]))

#define MMA_F16(d, a, b) \
    asm volatile("mma.sync.aligned.m16n8k16.row.col.f32.f16.f16.f32 " \
                 "{%0,%1,%2,%3},{%4,%5,%6,%7},{%8,%9},{%0,%1,%2,%3};" \
                 : "+f"(d[0]), "+f"(d[1]), "+f"(d[2]), "+f"(d[3]) \
                 : "r"(a[0]), "r"(a[1]), "r"(a[2]), "r"(a[3]), "r"(b[0]), "r"(b[1]))

__device__ __forceinline__ float sigm(float x){ return 1.f/(1.f + __expf(-x)); }

// ---------------- prep ----------------
__global__ void k_split_x(const float* __restrict__ x){
    int i = blockIdx.x*blockDim.x + threadIdx.x;
    int stride = gridDim.x*blockDim.x;
    for (; i < ROWS*HID; i += stride){
        float v = x[i];
        __nv_bfloat16 h = __float2bfloat16(v);
        g_xh[i] = h;
        g_xl[i] = __float2bfloat16(v - __bfloat162float(h));
    }
}

// transposed + gate-interleaved weights (col = 4*j + gate)
__global__ void k_prep_w(const float* Wii, const float* Wfi, const float* Wgi, const float* Woi,
                         const float* Wih, const float* Wfh, const float* Wgh, const float* Woh,
                         const float* bii, const float* bih, const float* bfi, const float* bfh,
                         const float* bgi, const float* bgh, const float* boi, const float* boh){
    size_t idx = (size_t)blockIdx.x*256 + threadIdx.x;
    if (idx >= (size_t)G4*HID) return;
    int c = (int)(idx >> 10), k = (int)(idx & 1023);
    int j = c >> 2, gg = c & 3;
    const float* wi = (gg==0)?Wii:(gg==1)?Wfi:(gg==2)?Wgi:Woi;
    const float* wh = (gg==0)?Wih:(gg==1)?Wfh:(gg==2)?Wgh:Woh;
    float vi = wi[(size_t)k*HID + j];
    float vh = wh[(size_t)k*HID + j];
    __nv_bfloat16 h1 = __float2bfloat16(vi);
    g_wih[idx] = h1; g_wil[idx] = __float2bfloat16(vi - __bfloat162float(h1));
    __half p1 = __float2half(vh);
    g_p1[idx] = p1;
    g_p2[idx] = __float2half(vh - __half2float(p1));
    if (idx < G4){
        int jj = (int)(idx >> 2); int g2 = (int)(idx & 3);
        const float* b1 = (g2==0)?bii:(g2==1)?bfi:(g2==2)?bgi:boi;
        const float* b2 = (g2==0)?bih:(g2==1)?bfh:(g2==2)?bgh:boh;
        g_bias[idx] = b1[jj] + b2[jj];
    }
}

__global__ void k_init(){
    int i = blockIdx.x*256 + threadIdx.x;
    __half z = __float2half(0.f);
    g_hf[0][i] = z; g_hf[1][i] = z;
    if (i < NCTA) g_flag[i] = 0;
}

// ---------------- xproj GEMM [32768,1024]x[1024,4096], 3-term bf16 (unchanged) ----
#define XP_STAGE 24576
#define RB 48

__global__ void __launch_bounds__(256) k_xproj(){
    extern __shared__ __align__(16) char smem_raw[];
    const uint32_t sbase = cvta_s(smem_raw);
    int tid = threadIdx.x;
    int lane = tid & 31, warp = tid >> 5;
    int g = lane >> 2, tq = lane & 3;
    int wm = warp >> 2, wn = warp & 3;
    int m0 = blockIdx.y * 128, n0 = blockIdx.x * 128;

    auto stage_load = [&](int kt, int s){
        int arr = tid >> 7, rem = tid & 127;
        int chunk = rem & 1, rc = rem >> 1;
        const __nv_bfloat16* gA = arr ? g_xl : g_xh;
        const __nv_bfloat16* gB = arr ? g_wil : g_wih;
        uint32_t aA = sbase + s*XP_STAGE + arr*6144;
        uint32_t aB = sbase + s*XP_STAGE + 12288 + arr*6144;
        #pragma unroll
        for (int i = 0; i < 2; i++){
            int row = rc + i*64;
            cpa16(aA + row*RB + chunk*16, gA + (size_t)(m0+row)*HID + kt*16 + chunk*8);
            cpa16(aB + row*RB + chunk*16, gB + (size_t)(n0+row)*HID + kt*16 + chunk*8);
        }
        CP_COMMIT();
    };

    stage_load(0, 0);
    stage_load(1, 1);

    float acc[4][4][4];
    #pragma unroll
    for (int ma = 0; ma < 4; ma++)
        #pragma unroll
        for (int na = 0; na < 4; na++){
            int c = n0 + wn*32 + na*8 + 2*tq;
            float b0 = g_bias[c], b1 = g_bias[c+1];
            acc[ma][na][0] = b0; acc[ma][na][1] = b1;
            acc[ma][na][2] = b0; acc[ma][na][3] = b1;
        }

    for (int kt = 0; kt < 64; kt++){
        CP_WAIT(1);
        __syncthreads();
        if (kt + 2 < 64) stage_load(kt + 2, (kt + 2) % 3);
        else CP_COMMIT();

        uint32_t st = sbase + (kt % 3)*XP_STAGE;
        uint32_t Ah = st, Al = st + 6144, Bh = st + 12288, Bl = st + 18432;
        uint32_t ah[4][4], al[4][4], bh[4][2], bl[4][2];
        #pragma unroll
        for (int ma = 0; ma < 4; ma++){
            int r = wm*64 + ma*16 + g;
            uint32_t o0 = r*RB + tq*4, o1 = (r+8)*RB + tq*4;
            ah[ma][0] = lds32(Ah + o0);      ah[ma][1] = lds32(Ah + o1);
            ah[ma][2] = lds32(Ah + o0 + 16); ah[ma][3] = lds32(Ah + o1 + 16);
            al[ma][0] = lds32(Al + o0);      al[ma][1] = lds32(Al + o1);
            al[ma][2] = lds32(Al + o0 + 16); al[ma][3] = lds32(Al + o1 + 16);
        }
        #pragma unroll
        for (int na = 0; na < 4; na++){
            int cb = wn*32 + na*8 + g;
            uint32_t o = cb*RB + tq*4;
            bh[na][0] = lds32(Bh + o); bh[na][1] = lds32(Bh + o + 16);
            bl[na][0] = lds32(Bl + o); bl[na][1] = lds32(Bl + o + 16);
        }
        #pragma unroll
        for (int ma = 0; ma < 4; ma++)
            #pragma unroll
            for (int na = 0; na < 4; na++){
                MMA_BF16(acc[ma][na], ah[ma], bh[na]);
                MMA_BF16(acc[ma][na], ah[ma], bl[na]);
                MMA_BF16(acc[ma][na], al[ma], bh[na]);
            }
    }

    CP_WAIT(0);
    __syncthreads();
    float* sOut = (float*)smem_raw;  // 128 x 132
    #pragma unroll
    for (int ma = 0; ma < 4; ma++)
        #pragma unroll
        for (int na = 0; na < 4; na++){
            int r = wm*64 + ma*16 + g;
            int c = wn*32 + na*8 + 2*tq;
            sOut[r*132 + c]       = acc[ma][na][0];
            sOut[r*132 + c + 1]   = acc[ma][na][1];
            sOut[(r+8)*132 + c]   = acc[ma][na][2];
            sOut[(r+8)*132 + c+1] = acc[ma][na][3];
        }
    __syncthreads();
    #pragma unroll
    for (int it = 0; it < 16; it++){
        int r2 = (tid >> 5) + it*8;
        int rg = m0 + r2;
        int b = rg >> 9, s = rg & 511;
        float4 v = *(float4*)(sOut + r2*132 + lane*4);
        *(float4*)(g_xproj + ((size_t)(s*64 + b))*G4 + n0 + lane*4) = v;
    }
}

// ---------------- persistent fp16 2-term recurrence ----------------
// D[64 x 64] = h[64,1024]f16 x [w1 ; w2][64rows,1024]f16 ; gates = D[:,0:32]+D[:,32:64]
// SMEM (bytes), pitch 144 (conflict-free):
//   [0, 147456)         B resident: 16 chunks x 64 rows x 144
//   [147456, 184320)    A stages: 4 x 9216 (64 rows x 144)
//   [184320, 193536)    sG0: 64 x 36 floats
//   [193536, 202752)    sG1: 64 x 36 floats
#define RQ_B    0u
#define RQ_A    147456u
#define RQ_SG0  184320u
#define RQ_SG1  193536u
#define RQ_SMEM 202752
#define PIT     144u

__global__ void __launch_bounds__(256, 1) k_recur(float* __restrict__ out){
    extern __shared__ __align__(16) char smem_raw[];
    const uint32_t sbase = cvta_s(smem_raw);
    float* sG0 = (float*)(smem_raw + RQ_SG0);
    float* sG1 = (float*)(smem_raw + RQ_SG1);
    int tid = threadIdx.x;
    int lane = tid & 31, warp = tid >> 5;
    int g = lane >> 2, tq = lane & 3;
    int wm = warp & 3, wn = warp >> 2;       // 4 m-tiles x 2 n-halves (w1/w2)
    int n0 = blockIdx.x * 32;

    // ---- resident [w1;w2] slice (once): 16 chunks x 64 rows x 128B ----
    for (int i = tid; i < 8192; i += 256){
        int ch = i >> 9, r = (i >> 3) & 63, c16 = i & 7;
        uint32_t dst = sbase + RQ_B + (uint32_t)ch*9216u + (uint32_t)r*PIT
                     + (uint32_t)c16*16u;
        const __half* src = (r < 32 ? g_p1 + (size_t)(n0 + r)*HID
                                    : g_p2 + (size_t)(n0 + r - 32)*HID)
                            + ch*64 + c16*8;
        cpa16(dst, src);
    }
    CP_COMMIT();

    float cst[2] = {0.f, 0.f};

    for (int t = 0; t < SS; t++){
        const __half* hin = g_hf[t & 1];

        auto load_chunk = [&](int c){
            #pragma unroll
            for (int rep = 0; rep < 2; rep++){
                int j = tid + rep*256;           // 0..511
                int R = j >> 3, c16 = j & 7;
                uint32_t dst = sbase + RQ_A + (uint32_t)(c & 3)*9216u
                             + (uint32_t)R*PIT + (uint32_t)c16*16u;
                cpa16(dst, hin + (size_t)R*HID + c*64 + c16*8);
            }
            CP_COMMIT();
        };

        load_chunk(0); load_chunk(1); load_chunk(2);

        // prefetch xproj slice (independent of h)
        float4 xv[2];
        #pragma unroll
        for (int p = 0; p < 2; p++){
            int b = p*32 + (tid >> 3), jl = tid & 7;
            xv[p] = *(const float4*)(g_xproj + ((size_t)t*BB + b)*G4 + n0 + jl*4);
        }

        float acc[4][4];
        #pragma unroll
        for (int nf = 0; nf < 4; nf++)
            #pragma unroll
            for (int k = 0; k < 4; k++) acc[nf][k] = 0.f;

        for (int c = 0; c < 16; c++){
            CP_WAIT(2);
            __syncthreads();
            if (c + 3 < 16) load_chunk(c + 3);
            else CP_COMMIT();

            uint32_t Ab = sbase + RQ_A + (uint32_t)(c & 3)*9216u;
            uint32_t Bb = sbase + RQ_B + (uint32_t)c*9216u;
            #pragma unroll
            for (int k = 0; k < 4; k++){
                uint32_t kb = (uint32_t)k*32u;
                uint32_t a[4];
                {
                    uint32_t o0 = (uint32_t)(wm*16 + g)*PIT + kb + tq*4;
                    uint32_t o1 = o0 + 8*PIT;
                    a[0] = lds32(Ab + o0);      a[1] = lds32(Ab + o1);
                    a[2] = lds32(Ab + o0 + 16); a[3] = lds32(Ab + o1 + 16);
                }
                #pragma unroll
                for (int nf = 0; nf < 4; nf++){
                    uint32_t o = (uint32_t)(wn*32 + nf*8 + g)*PIT + kb + tq*4;
                    uint32_t b[2];
                    b[0] = lds32(Bb + o); b[1] = lds32(Bb + o + 16);
                    MMA_F16(acc[nf], a, b);
                }
            }
        }

        // ---- epilogue: each wn-half to its own buffer ----
        float* sG = wn ? sG1 : sG0;
        #pragma unroll
        for (int nf = 0; nf < 4; nf++){
            int r = wm*16 + g;
            int cc = nf*8 + 2*tq;
            sG[r*36 + cc]       = acc[nf][0];
            sG[r*36 + cc + 1]   = acc[nf][1];
            sG[(r+8)*36 + cc]   = acc[nf][2];
            sG[(r+8)*36 + cc+1] = acc[nf][3];
        }
        __syncthreads();

        bool last = (t == SS - 1);
        __half* hout = g_hf[(t + 1) & 1];
        #pragma unroll
        for (int p = 0; p < 2; p++){
            int b = p*32 + (tid >> 3), jl = tid & 7;
            float4 g0 = *(float4*)(sG0 + b*36 + jl*4);
            float4 g1 = *(float4*)(sG1 + b*36 + jl*4);
            float iv = sigm(g0.x + g1.x + xv[p].x);
            float fv = sigm(g0.y + g1.y + xv[p].y);
            float gv = tanhf(g0.z + g1.z + xv[p].z);
            float ov = sigm(g0.w + g1.w + xv[p].w);
            float cn = fv*cst[p] + iv*gv;
            cst[p] = cn;
            float h = ov*tanhf(cn);
            int ci = b*HID + (n0 >> 2) + jl;
            __half hq = __float2half(h);
            asm volatile("st.global.cg.u16 [%0], %1;" :: "l"(hout + ci),
                         "h"(*(const unsigned short*)&hq));
            if (last){ out[ci] = h; out[BB*HID + ci] = cn; }
        }
        __syncthreads();

        // ---- distributed grid barrier ----
        if (tid == 0){
            __threadfence();
            asm volatile("st.global.release.gpu.s32 [%0], %1;"
                         :: "l"(g_flag + blockIdx.x), "r"(t + 1) : "memory");
        }
        if (tid < NCTA){
            int v;
            do {
                asm volatile("ld.global.acquire.gpu.s32 %0, [%1];"
                             : "=r"(v) : "l"(g_flag + tid));
            } while (v < t + 1);
        }
        __syncthreads();
    }
}

// ---------------- launch ----------------
extern "C" void kernel_launch(void* const* d_in, const int* in_sizes, int n_in,
                              void* d_out, int out_size){
    // dict order: x, Wii,Wfi,Wgi,Woi, Wih,Wfh,Wgh,Woh, bii,bih,bfi,bfh,bgi,bgh,boi,boh
    const float* x = nullptr;
    const float* w[8] = {nullptr}; const float* bp[8] = {nullptr};
    int nw = 0, nb = 0;
    for (int i = 0; i < n_in; i++){
        if (in_sizes[i] == ROWS*HID)      x = (const float*)d_in[i];
        else if (in_sizes[i] == HID*HID){ if (nw < 8) w[nw++] = (const float*)d_in[i]; }
        else if (in_sizes[i] == HID){     if (nb < 8) bp[nb++] = (const float*)d_in[i]; }
    }
    float* out = (float*)d_out;

    cudaFuncSetAttribute(k_xproj, cudaFuncAttributeMaxDynamicSharedMemorySize, 3*XP_STAGE);
    cudaFuncSetAttribute(k_recur, cudaFuncAttributeMaxDynamicSharedMemorySize, RQ_SMEM);

    k_split_x<<<2048, 256>>>(x);
    k_prep_w<<<16384, 256>>>(w[0], w[1], w[2], w[3], w[4], w[5], w[6], w[7],
                             bp[0], bp[1], bp[2], bp[3], bp[4], bp[5], bp[6], bp[7]);
    k_init<<<256, 256>>>();
    dim3 gx(32, 256);
    k_xproj<<<gx, 256, 3*XP_STAGE>>>();
    k_recur<<<NCTA, 256, RQ_SMEM>>>(out);
}

// round 16
// speedup vs baseline: 1.7634x; 1.1192x over previous
#include <cuda_runtime.h>
#include <cuda_bf16.h>
#include <cuda_fp16.h>
#include <cstdint>
#include <math.h>

#define BB   64
#define SS   512
#define HID  1024
#define G4   4096
#define ROWS (BB*SS)
#define NCTA 128

// ---------------- device scratch ----------------
__device__ __half g_xf[ROWS*HID];            // x as fp16
__device__ __half g_wf1[(size_t)G4*HID];     // Wi fp16 digit1 (transposed+interleaved)
__device__ __half g_wf2[(size_t)G4*HID];     // Wi fp16 digit2
__device__ __half g_p1[(size_t)G4*HID];      // Wh fp16 (single term)
__device__ float g_bias[G4];
__device__ float g_xproj[(size_t)SS*BB*G4];
__device__ __half g_hf[2][BB*HID];           // h fp16 ping-pong
__device__ int g_flag[NCTA];

// ---------------- helpers ----------------
__device__ __forceinline__ uint32_t cvta_s(const void* p){
    return (uint32_t)__cvta_generic_to_shared(p);
}
__device__ __forceinline__ uint32_t lds32(uint32_t a){
    uint32_t v; asm volatile("ld.shared.b32 %0,[%1];" : "=r"(v) : "r"(a)); return v;
}
__device__ __forceinline__ void cpa16(uint32_t s, const void* g){
    asm volatile("cp.async.cg.shared.global [%0],[%1],16;" :: "r"(s), "l"(g));
}
#define CP_COMMIT() asm volatile("cp.async.commit_group;")
#define CP_WAIT(N)  asm volatile("cp.async.wait_group %0;" :: "n"(N))

#define MMA_F16(d, a, b) \
    asm volatile("mma.sync.aligned.m16n8k16.row.col.f32.f16.f16.f32 " \
                 "{%0,%1,%2,%3},{%4,%5,%6,%7},{%8,%9},{%0,%1,%2,%3};" \
                 : "+f"(d[0]), "+f"(d[1]), "+f"(d[2]), "+f"(d[3]) \
                 : "r"(a[0]), "r"(a[1]), "r"(a[2]), "r"(a[3]), "r"(b[0]), "r"(b[1]))

__device__ __forceinline__ float sigm(float x){ return 1.f/(1.f + __expf(-x)); }

// ---------------- prep ----------------
__global__ void k_split_x(const float* __restrict__ x){
    int i = blockIdx.x*blockDim.x + threadIdx.x;
    int stride = gridDim.x*blockDim.x;
    for (; i < ROWS*HID; i += stride)
        g_xf[i] = __float2half(x[i]);
}

// transposed + gate-interleaved weights (col = 4*j + gate)
__global__ void k_prep_w(const float* Wii, const float* Wfi, const float* Wgi, const float* Woi,
                         const float* Wih, const float* Wfh, const float* Wgh, const float* Woh,
                         const float* bii, const float* bih, const float* bfi, const float* bfh,
                         const float* bgi, const float* bgh, const float* boi, const float* boh){
    size_t idx = (size_t)blockIdx.x*256 + threadIdx.x;
    if (idx >= (size_t)G4*HID) return;
    int c = (int)(idx >> 10), k = (int)(idx & 1023);
    int j = c >> 2, gg = c & 3;
    const float* wi = (gg==0)?Wii:(gg==1)?Wfi:(gg==2)?Wgi:Woi;
    const float* wh = (gg==0)?Wih:(gg==1)?Wfh:(gg==2)?Wgh:Woh;
    float vi = wi[(size_t)k*HID + j];
    float vh = wh[(size_t)k*HID + j];
    __half w1 = __float2half(vi);
    g_wf1[idx] = w1;
    g_wf2[idx] = __float2half(vi - __half2float(w1));
    g_p1[idx]  = __float2half(vh);
    if (idx < G4){
        int jj = (int)(idx >> 2); int g2 = (int)(idx & 3);
        const float* b1 = (g2==0)?bii:(g2==1)?bfi:(g2==2)?bgi:boi;
        const float* b2 = (g2==0)?bih:(g2==1)?bfh:(g2==2)?bgh:boh;
        g_bias[idx] = b1[jj] + b2[jj];
    }
}

__global__ void k_init(){
    int i = blockIdx.x*256 + threadIdx.x;
    __half z = __float2half(0.f);
    g_hf[0][i] = z; g_hf[1][i] = z;
    if (i < NCTA) g_flag[i] = 0;
}

// ---------------- xproj GEMM [32768,1024]x[1024,4096], 2-term fp16, tile 128x128 ----
// Stage (18432 B): A[0,6144) B1[6144,12288) B2[12288,18432); 128 rows x 48B pitch
#define XP_STAGE 18432
#define XP_SMEM  67584     // max(3 stages 55296, sOut 128*132*4)
#define RB 48

__global__ void __launch_bounds__(256) k_xproj(){
    extern __shared__ __align__(16) char smem_raw[];
    const uint32_t sbase = cvta_s(smem_raw);
    int tid = threadIdx.x;
    int lane = tid & 31, warp = tid >> 5;
    int g = lane >> 2, tq = lane & 3;
    int wm = warp >> 2, wn = warp & 3;
    int m0 = blockIdx.y * 128, n0 = blockIdx.x * 128;

    auto stage_load = [&](int kt, int s){
        int chunk = tid & 1, rc = tid >> 1;      // rc 0..127
        uint32_t st = sbase + s*XP_STAGE;
        cpa16(st + rc*RB + chunk*16,
              g_xf  + (size_t)(m0+rc)*HID + kt*16 + chunk*8);
        cpa16(st + 6144 + rc*RB + chunk*16,
              g_wf1 + (size_t)(n0+rc)*HID + kt*16 + chunk*8);
        cpa16(st + 12288 + rc*RB + chunk*16,
              g_wf2 + (size_t)(n0+rc)*HID + kt*16 + chunk*8);
        CP_COMMIT();
    };

    stage_load(0, 0);
    stage_load(1, 1);

    float acc[4][4][4];
    #pragma unroll
    for (int ma = 0; ma < 4; ma++)
        #pragma unroll
        for (int na = 0; na < 4; na++){
            int c = n0 + wn*32 + na*8 + 2*tq;
            float b0 = g_bias[c], b1 = g_bias[c+1];
            acc[ma][na][0] = b0; acc[ma][na][1] = b1;
            acc[ma][na][2] = b0; acc[ma][na][3] = b1;
        }

    for (int kt = 0; kt < 64; kt++){
        CP_WAIT(1);
        __syncthreads();
        if (kt + 2 < 64) stage_load(kt + 2, (kt + 2) % 3);
        else CP_COMMIT();

        uint32_t st = sbase + (kt % 3)*XP_STAGE;
        uint32_t Ab = st, B1 = st + 6144, B2 = st + 12288;
        uint32_t a[4][4], bh[4][2], bl[4][2];
        #pragma unroll
        for (int ma = 0; ma < 4; ma++){
            int r = wm*64 + ma*16 + g;
            uint32_t o0 = r*RB + tq*4, o1 = (r+8)*RB + tq*4;
            a[ma][0] = lds32(Ab + o0);      a[ma][1] = lds32(Ab + o1);
            a[ma][2] = lds32(Ab + o0 + 16); a[ma][3] = lds32(Ab + o1 + 16);
        }
        #pragma unroll
        for (int na = 0; na < 4; na++){
            int cb = wn*32 + na*8 + g;
            uint32_t o = cb*RB + tq*4;
            bh[na][0] = lds32(B1 + o); bh[na][1] = lds32(B1 + o + 16);
            bl[na][0] = lds32(B2 + o); bl[na][1] = lds32(B2 + o + 16);
        }
        #pragma unroll
        for (int ma = 0; ma < 4; ma++)
            #pragma unroll
            for (int na = 0; na < 4; na++){
                MMA_F16(acc[ma][na], a[ma], bh[na]);
                MMA_F16(acc[ma][na], a[ma], bl[na]);
            }
    }

    CP_WAIT(0);
    __syncthreads();
    float* sOut = (float*)smem_raw;  // 128 x 132
    #pragma unroll
    for (int ma = 0; ma < 4; ma++)
        #pragma unroll
        for (int na = 0; na < 4; na++){
            int r = wm*64 + ma*16 + g;
            int c = wn*32 + na*8 + 2*tq;
            sOut[r*132 + c]       = acc[ma][na][0];
            sOut[r*132 + c + 1]   = acc[ma][na][1];
            sOut[(r+8)*132 + c]   = acc[ma][na][2];
            sOut[(r+8)*132 + c+1] = acc[ma][na][3];
        }
    __syncthreads();
    #pragma unroll
    for (int it = 0; it < 16; it++){
        int r2 = (tid >> 5) + it*8;
        int rg = m0 + r2;
        int b = rg >> 9, s = rg & 511;
        float4 v = *(float4*)(sOut + r2*132 + lane*4);
        *(float4*)(g_xproj + ((size_t)(s*64 + b))*G4 + n0 + lane*4) = v;
    }
}

// ---------------- persistent fp16 1-term recurrence ----------------
// D[64 x 32] = h[64,1024]f16 x Wh[32rows,1024]f16
// SMEM (bytes), pitch 144 (conflict-free):
//   [0, 73728)        B resident: 16 chunks x 32 rows x 144
//   [73728, 110592)   A stages: 4 x 9216 (64 rows x 144)
//   [110592, 119808)  sG: 64 x 36 floats
#define RQ_B    0u
#define RQ_A    73728u
#define RQ_SG   110592u
#define RQ_SMEM 119808
#define PIT     144u

__global__ void __launch_bounds__(256, 1) k_recur(float* __restrict__ out){
    extern __shared__ __align__(16) char smem_raw[];
    const uint32_t sbase = cvta_s(smem_raw);
    float* sG = (float*)(smem_raw + RQ_SG);
    int tid = threadIdx.x;
    int lane = tid & 31, warp = tid >> 5;
    int g = lane >> 2, tq = lane & 3;
    int wm = warp & 3, wn = warp >> 2;       // 4 m-tiles x 2 n-halves
    int n0 = blockIdx.x * 32;

    // ---- resident Wh slice (once): 16 chunks x 32 rows x 128B ----
    for (int i = tid; i < 4096; i += 256){
        int ch = i >> 8, r = (i >> 3) & 31, c16 = i & 7;
        uint32_t dst = sbase + RQ_B + (uint32_t)ch*4608u + (uint32_t)r*PIT
                     + (uint32_t)c16*16u;
        cpa16(dst, g_p1 + (size_t)(n0 + r)*HID + ch*64 + c16*8);
    }
    CP_COMMIT();

    float cst[2] = {0.f, 0.f};

    for (int t = 0; t < SS; t++){
        const __half* hin = g_hf[t & 1];

        auto load_chunk = [&](int c){
            #pragma unroll
            for (int rep = 0; rep < 2; rep++){
                int j = tid + rep*256;           // 0..511
                int R = j >> 3, c16 = j & 7;
                uint32_t dst = sbase + RQ_A + (uint32_t)(c & 3)*9216u
                             + (uint32_t)R*PIT + (uint32_t)c16*16u;
                cpa16(dst, hin + (size_t)R*HID + c*64 + c16*8);
            }
            CP_COMMIT();
        };

        load_chunk(0); load_chunk(1); load_chunk(2);

        // prefetch xproj slice (independent of h)
        float4 xv[2];
        #pragma unroll
        for (int p = 0; p < 2; p++){
            int b = p*32 + (tid >> 3), jl = tid & 7;
            xv[p] = *(const float4*)(g_xproj + ((size_t)t*BB + b)*G4 + n0 + jl*4);
        }

        float acc[2][4];
        #pragma unroll
        for (int nf = 0; nf < 2; nf++)
            #pragma unroll
            for (int k = 0; k < 4; k++) acc[nf][k] = 0.f;

        for (int c = 0; c < 16; c++){
            CP_WAIT(2);
            __syncthreads();
            if (c + 3 < 16) load_chunk(c + 3);
            else CP_COMMIT();

            uint32_t Ab = sbase + RQ_A + (uint32_t)(c & 3)*9216u;
            uint32_t Bb = sbase + RQ_B + (uint32_t)c*4608u;
            #pragma unroll
            for (int k = 0; k < 4; k++){
                uint32_t kb = (uint32_t)k*32u;
                uint32_t a[4];
                {
                    uint32_t o0 = (uint32_t)(wm*16 + g)*PIT + kb + tq*4;
                    uint32_t o1 = o0 + 8*PIT;
                    a[0] = lds32(Ab + o0);      a[1] = lds32(Ab + o1);
                    a[2] = lds32(Ab + o0 + 16); a[3] = lds32(Ab + o1 + 16);
                }
                #pragma unroll
                for (int nf = 0; nf < 2; nf++){
                    uint32_t o = (uint32_t)(wn*16 + nf*8 + g)*PIT + kb + tq*4;
                    uint32_t b[2];
                    b[0] = lds32(Bb + o); b[1] = lds32(Bb + o + 16);
                    MMA_F16(acc[nf], a, b);
                }
            }
        }

        // ---- epilogue ----
        #pragma unroll
        for (int nf = 0; nf < 2; nf++){
            int r = wm*16 + g;
            int cc = wn*16 + nf*8 + 2*tq;
            sG[r*36 + cc]       = acc[nf][0];
            sG[r*36 + cc + 1]   = acc[nf][1];
            sG[(r+8)*36 + cc]   = acc[nf][2];
            sG[(r+8)*36 + cc+1] = acc[nf][3];
        }
        __syncthreads();

        bool last = (t == SS - 1);
        __half* hout = g_hf[(t + 1) & 1];
        #pragma unroll
        for (int p = 0; p < 2; p++){
            int b = p*32 + (tid >> 3), jl = tid & 7;
            float4 g0 = *(float4*)(sG + b*36 + jl*4);
            float iv = sigm(g0.x + xv[p].x);
            float fv = sigm(g0.y + xv[p].y);
            float gv = tanhf(g0.z + xv[p].z);
            float ov = sigm(g0.w + xv[p].w);
            float cn = fv*cst[p] + iv*gv;
            cst[p] = cn;
            float h = ov*tanhf(cn);
            int ci = b*HID + (n0 >> 2) + jl;
            __half hq = __float2half(h);
            asm volatile("st.global.cg.u16 [%0], %1;" :: "l"(hout + ci),
                         "h"(*(const unsigned short*)&hq));
            if (last){ out[ci] = h; out[BB*HID + ci] = cn; }
        }
        __syncthreads();

        // ---- distributed grid barrier ----
        if (tid == 0){
            __threadfence();
            asm volatile("st.global.release.gpu.s32 [%0], %1;"
                         :: "l"(g_flag + blockIdx.x), "r"(t + 1) : "memory");
        }
        if (tid < NCTA){
            int v;
            do {
                asm volatile("ld.global.acquire.gpu.s32 %0, [%1];"
                             : "=r"(v) : "l"(g_flag + tid));
            } while (v < t + 1);
        }
        __syncthreads();
    }
}

// ---------------- launch ----------------
extern "C" void kernel_launch(void* const* d_in, const int* in_sizes, int n_in,
                              void* d_out, int out_size){
    // dict order: x, Wii,Wfi,Wgi,Woi, Wih,Wfh,Wgh,Woh, bii,bih,bfi,bfh,bgi,bgh,boi,boh
    const float* x = nullptr;
    const float* w[8] = {nullptr}; const float* bp[8] = {nullptr};
    int nw = 0, nb = 0;
    for (int i = 0; i < n_in; i++){
        if (in_sizes[i] == ROWS*HID)      x = (const float*)d_in[i];
        else if (in_sizes[i] == HID*HID){ if (nw < 8) w[nw++] = (const float*)d_in[i]; }
        else if (in_sizes[i] == HID){     if (nb < 8) bp[nb++] = (const float*)d_in[i]; }
    }
    float* out = (float*)d_out;

    cudaFuncSetAttribute(k_xproj, cudaFuncAttributeMaxDynamicSharedMemorySize, XP_SMEM);
    cudaFuncSetAttribute(k_recur, cudaFuncAttributeMaxDynamicSharedMemorySize, RQ_SMEM);

    k_split_x<<<2048, 256>>>(x);
    k_prep_w<<<16384, 256>>>(w[0], w[1], w[2], w[3], w[4], w[5], w[6], w[7],
                             bp[0], bp[1], bp[2], bp[3], bp[4], bp[5], bp[6], bp[7]);
    k_init<<<256, 256>>>();
    dim3 gx(32, 256);
    k_xproj<<<gx, 256, XP_SMEM>>>();
    k_recur<<<NCTA, 256, RQ_SMEM>>>(out);
}

// round 17
// speedup vs baseline: 1.9990x; 1.1336x over previous
#include <cuda_runtime.h>
#include <cuda_bf16.h>
#include <cuda_fp16.h>
#include <cstdint>
#include <math.h>

#define BB   64
#define SS   512
#define HID  1024
#define G4   4096
#define ROWS (BB*SS)
#define NCTA 128
#define HPIT 1032            // h row pitch in halfs (2064 B)

// ---------------- device scratch ----------------
__device__ __half g_xf[ROWS*HID];            // x as fp16
__device__ __half g_wf1[(size_t)G4*HID];     // Wi fp16 digit1 (transposed+interleaved)
__device__ __half g_wf2[(size_t)G4*HID];     // Wi fp16 digit2
__device__ __half g_p1[(size_t)G4*HID];      // Wh fp16 (single term)
__device__ float g_bias[G4];
__device__ float g_xproj[(size_t)SS*BB*G4];
__device__ __align__(256) __half g_hf[2][BB*HPIT];  // h fp16, pitched, ping-pong
__device__ int g_flag[NCTA];

// ---------------- helpers ----------------
__device__ __forceinline__ uint32_t cvta_s(const void* p){
    return (uint32_t)__cvta_generic_to_shared(p);
}
__device__ __forceinline__ uint32_t lds32(uint32_t a){
    uint32_t v; asm volatile("ld.shared.b32 %0,[%1];" : "=r"(v) : "r"(a)); return v;
}
__device__ __forceinline__ void cpa16(uint32_t s, const void* g){
    asm volatile("cp.async.cg.shared.global [%0],[%1],16;" :: "r"(s), "l"(g));
}
#define CP_COMMIT() asm volatile("cp.async.commit_group;")
#define CP_WAIT(N)  asm volatile("cp.async.wait_group %0;" :: "n"(N))

#define MMA_F16(d, a, b) \
    asm volatile("mma.sync.aligned.m16n8k16.row.col.f32.f16.f16.f32 " \
                 "{%0,%1,%2,%3},{%4,%5,%6,%7},{%8,%9},{%0,%1,%2,%3};" \
                 : "+f"(d[0]), "+f"(d[1]), "+f"(d[2]), "+f"(d[3]) \
                 : "r"(a[0]), "r"(a[1]), "r"(a[2]), "r"(a[3]), "r"(b[0]), "r"(b[1]))

__device__ __forceinline__ float sigm(float x){ return 1.f/(1.f + __expf(-x)); }

__device__ __forceinline__ void mbar_init(uint32_t a){
    asm volatile("mbarrier.init.shared.b64 [%0], 1;" :: "r"(a) : "memory");
}
__device__ __forceinline__ void mbar_expect_tx(uint32_t a, uint32_t bytes){
    asm volatile("mbarrier.arrive.expect_tx.shared.b64 _, [%0], %1;"
                 :: "r"(a), "r"(bytes) : "memory");
}
__device__ __forceinline__ void mbar_wait(uint32_t a, uint32_t parity){
    asm volatile("{\n\t.reg .pred P;\n\tWL_%=:\n\t"
        "mbarrier.try_wait.parity.acquire.cta.shared::cta.b64 P, [%0], %1, 0x989680;\n\t"
        "@!P bra WL_%=;\n\t}" :: "r"(a), "r"(parity) : "memory");
}
__device__ __forceinline__ void bulk_g2s(uint32_t dst, const void* src,
                                         uint32_t bytes, uint32_t mbar){
    asm volatile("cp.async.bulk.shared::cluster.global.mbarrier::complete_tx::bytes "
                 "[%0], [%1], %2, [%3];"
                 :: "r"(dst), "l"(src), "r"(bytes), "r"(mbar) : "memory");
}

// ---------------- prep ----------------
__global__ void k_split_x(const float* __restrict__ x){
    int i = blockIdx.x*blockDim.x + threadIdx.x;
    int stride = gridDim.x*blockDim.x;
    for (; i < ROWS*HID; i += stride)
        g_xf[i] = __float2half(x[i]);
}

// transposed + gate-interleaved weights (col = 4*j + gate)
__global__ void k_prep_w(const float* Wii, const float* Wfi, const float* Wgi, const float* Woi,
                         const float* Wih, const float* Wfh, const float* Wgh, const float* Woh,
                         const float* bii, const float* bih, const float* bfi, const float* bfh,
                         const float* bgi, const float* bgh, const float* boi, const float* boh){
    size_t idx = (size_t)blockIdx.x*256 + threadIdx.x;
    if (idx >= (size_t)G4*HID) return;
    int c = (int)(idx >> 10), k = (int)(idx & 1023);
    int j = c >> 2, gg = c & 3;
    const float* wi = (gg==0)?Wii:(gg==1)?Wfi:(gg==2)?Wgi:Woi;
    const float* wh = (gg==0)?Wih:(gg==1)?Wfh:(gg==2)?Wgh:Woh;
    float vi = wi[(size_t)k*HID + j];
    float vh = wh[(size_t)k*HID + j];
    __half w1 = __float2half(vi);
    g_wf1[idx] = w1;
    g_wf2[idx] = __float2half(vi - __half2float(w1));
    g_p1[idx]  = __float2half(vh);
    if (idx < G4){
        int jj = (int)(idx >> 2); int g2 = (int)(idx & 3);
        const float* b1 = (g2==0)?bii:(g2==1)?bfi:(g2==2)?bgi:boi;
        const float* b2 = (g2==0)?bih:(g2==1)?bfh:(g2==2)?bgh:boh;
        g_bias[idx] = b1[jj] + b2[jj];
    }
}

__global__ void k_init(){
    int i0 = blockIdx.x*256 + threadIdx.x;
    __half z = __float2half(0.f);
    for (int i = i0; i < BB*HPIT; i += 65536){
        g_hf[0][i] = z; g_hf[1][i] = z;
    }
    if (i0 < NCTA) g_flag[i0] = 0;
}

// ---------------- xproj GEMM [32768,1024]x[1024,4096], 2-term fp16, tile 128x128 ----
// Stage (18432 B): A[0,6144) B1[6144,12288) B2[12288,18432); 128 rows x 48B pitch
#define XP_STAGE 18432
#define XP_SMEM  67584
#define RB 48

__global__ void __launch_bounds__(256) k_xproj(){
    extern __shared__ __align__(16) char smem_raw[];
    const uint32_t sbase = cvta_s(smem_raw);
    int tid = threadIdx.x;
    int lane = tid & 31, warp = tid >> 5;
    int g = lane >> 2, tq = lane & 3;
    int wm = warp >> 2, wn = warp & 3;
    int m0 = blockIdx.y * 128, n0 = blockIdx.x * 128;

    auto stage_load = [&](int kt, int s){
        int chunk = tid & 1, rc = tid >> 1;      // rc 0..127
        uint32_t st = sbase + s*XP_STAGE;
        cpa16(st + rc*RB + chunk*16,
              g_xf  + (size_t)(m0+rc)*HID + kt*16 + chunk*8);
        cpa16(st + 6144 + rc*RB + chunk*16,
              g_wf1 + (size_t)(n0+rc)*HID + kt*16 + chunk*8);
        cpa16(st + 12288 + rc*RB + chunk*16,
              g_wf2 + (size_t)(n0+rc)*HID + kt*16 + chunk*8);
        CP_COMMIT();
    };

    stage_load(0, 0);
    stage_load(1, 1);

    float acc[4][4][4];
    #pragma unroll
    for (int ma = 0; ma < 4; ma++)
        #pragma unroll
        for (int na = 0; na < 4; na++){
            int c = n0 + wn*32 + na*8 + 2*tq;
            float b0 = g_bias[c], b1 = g_bias[c+1];
            acc[ma][na][0] = b0; acc[ma][na][1] = b1;
            acc[ma][na][2] = b0; acc[ma][na][3] = b1;
        }

    for (int kt = 0; kt < 64; kt++){
        CP_WAIT(1);
        __syncthreads();
        if (kt + 2 < 64) stage_load(kt + 2, (kt + 2) % 3);
        else CP_COMMIT();

        uint32_t st = sbase + (kt % 3)*XP_STAGE;
        uint32_t Ab = st, B1 = st + 6144, B2 = st + 12288;
        uint32_t a[4][4], bh[4][2], bl[4][2];
        #pragma unroll
        for (int ma = 0; ma < 4; ma++){
            int r = wm*64 + ma*16 + g;
            uint32_t o0 = r*RB + tq*4, o1 = (r+8)*RB + tq*4;
            a[ma][0] = lds32(Ab + o0);      a[ma][1] = lds32(Ab + o1);
            a[ma][2] = lds32(Ab + o0 + 16); a[ma][3] = lds32(Ab + o1 + 16);
        }
        #pragma unroll
        for (int na = 0; na < 4; na++){
            int cb = wn*32 + na*8 + g;
            uint32_t o = cb*RB + tq*4;
            bh[na][0] = lds32(B1 + o); bh[na][1] = lds32(B1 + o + 16);
            bl[na][0] = lds32(B2 + o); bl[na][1] = lds32(B2 + o + 16);
        }
        #pragma unroll
        for (int ma = 0; ma < 4; ma++)
            #pragma unroll
            for (int na = 0; na < 4; na++){
                MMA_F16(acc[ma][na], a[ma], bh[na]);
                MMA_F16(acc[ma][na], a[ma], bl[na]);
            }
    }

    CP_WAIT(0);
    __syncthreads();
    float* sOut = (float*)smem_raw;  // 128 x 132
    #pragma unroll
    for (int ma = 0; ma < 4; ma++)
        #pragma unroll
        for (int na = 0; na < 4; na++){
            int r = wm*64 + ma*16 + g;
            int c = wn*32 + na*8 + 2*tq;
            sOut[r*132 + c]       = acc[ma][na][0];
            sOut[r*132 + c + 1]   = acc[ma][na][1];
            sOut[(r+8)*132 + c]   = acc[ma][na][2];
            sOut[(r+8)*132 + c+1] = acc[ma][na][3];
        }
    __syncthreads();
    #pragma unroll
    for (int it = 0; it < 16; it++){
        int r2 = (tid >> 5) + it*8;
        int rg = m0 + r2;
        int b = rg >> 9, s = rg & 511;
        float4 v = *(float4*)(sOut + r2*132 + lane*4);
        *(float4*)(g_xproj + ((size_t)(s*64 + b))*G4 + n0 + lane*4) = v;
    }
}

// ---------------- persistent fp16 recurrence, bulk-copy A ----------------
// D[64 x 32] = h[64,1024]f16 x Wh[32rows,1024]f16
// SMEM (bytes):
//   [0, 73728)         B resident: 16 chunks x 32 rows x 144 (pitch 144, conflict-free)
//   [73728, 205824)    A: 64 rows x 2064 B pitch (bulk-copied, banks 4*row+w)
//   [205824, 215040)   sG: 64 x 36 floats
//   [215040, 215048)   mbarrier
#define RQ_B    0u
#define RQ_A    73728u
#define RQ_SG   205824u
#define RQ_MB   215040u
#define RQ_SMEM 215072
#define PIT     144u
#define ABYTES  132096u      // 64 * 2064

__global__ void __launch_bounds__(256, 1) k_recur(float* __restrict__ out){
    extern __shared__ __align__(16) char smem_raw[];
    const uint32_t sbase = cvta_s(smem_raw);
    float* sG = (float*)(smem_raw + RQ_SG);
    int tid = threadIdx.x;
    int lane = tid & 31, warp = tid >> 5;
    int g = lane >> 2, tq = lane & 3;
    int wm = warp & 3, wn = warp >> 2;       // 4 m-tiles x 2 n-halves
    int n0 = blockIdx.x * 32;

    // ---- resident Wh slice (once): 16 chunks x 32 rows x 128B ----
    for (int i = tid; i < 4096; i += 256){
        int ch = i >> 8, r = (i >> 3) & 31, c16 = i & 7;
        uint32_t dst = sbase + RQ_B + (uint32_t)ch*4608u + (uint32_t)r*PIT
                     + (uint32_t)c16*16u;
        cpa16(dst, g_p1 + (size_t)(n0 + r)*HID + ch*64 + c16*8);
    }
    CP_COMMIT();
    if (tid == 0) mbar_init(sbase + RQ_MB);
    CP_WAIT(0);
    __syncthreads();

    // per-thread A/B address bases
    uint32_t aRow = sbase + RQ_A + (uint32_t)(wm*16 + g)*2064u + (uint32_t)tq*4u;
    float cst[2] = {0.f, 0.f};

    for (int t = 0; t < SS; t++){
        // ---- issue bulk copy of h(t) ----
        if (tid == 0){
            mbar_expect_tx(sbase + RQ_MB, ABYTES);
            bulk_g2s(sbase + RQ_A, g_hf[t & 1], ABYTES, sbase + RQ_MB);
        }

        // prefetch xproj slice (independent of h)
        float4 xv[2];
        #pragma unroll
        for (int p = 0; p < 2; p++){
            int b = p*32 + (tid >> 3), jl = tid & 7;
            xv[p] = *(const float4*)(g_xproj + ((size_t)t*BB + b)*G4 + n0 + jl*4);
        }

        mbar_wait(sbase + RQ_MB, (uint32_t)(t & 1));

        float acc[2][4];
        #pragma unroll
        for (int nf = 0; nf < 2; nf++)
            #pragma unroll
            for (int k = 0; k < 4; k++) acc[nf][k] = 0.f;

        #pragma unroll 8
        for (int kt = 0; kt < 64; kt++){
            uint32_t a[4];
            uint32_t ab = aRow + (uint32_t)kt*32u;
            a[0] = lds32(ab);              a[1] = lds32(ab + 8*2064u);
            a[2] = lds32(ab + 16);         a[3] = lds32(ab + 8*2064u + 16);
            uint32_t Bb = sbase + RQ_B + (uint32_t)(kt >> 2)*4608u
                        + (uint32_t)(kt & 3)*32u;
            #pragma unroll
            for (int nf = 0; nf < 2; nf++){
                uint32_t o = Bb + (uint32_t)(wn*16 + nf*8 + g)*PIT + tq*4;
                uint32_t b[2];
                b[0] = lds32(o); b[1] = lds32(o + 16);
                MMA_F16(acc[nf], a, b);
            }
        }

        // ---- epilogue ----
        #pragma unroll
        for (int nf = 0; nf < 2; nf++){
            int r = wm*16 + g;
            int cc = wn*16 + nf*8 + 2*tq;
            sG[r*36 + cc]       = acc[nf][0];
            sG[r*36 + cc + 1]   = acc[nf][1];
            sG[(r+8)*36 + cc]   = acc[nf][2];
            sG[(r+8)*36 + cc+1] = acc[nf][3];
        }
        __syncthreads();

        bool last = (t == SS - 1);
        __half* hout = g_hf[(t + 1) & 1];
        #pragma unroll
        for (int p = 0; p < 2; p++){
            int b = p*32 + (tid >> 3), jl = tid & 7;
            float4 g0 = *(float4*)(sG + b*36 + jl*4);
            float iv = sigm(g0.x + xv[p].x);
            float fv = sigm(g0.y + xv[p].y);
            float gv = tanhf(g0.z + xv[p].z);
            float ov = sigm(g0.w + xv[p].w);
            float cn = fv*cst[p] + iv*gv;
            cst[p] = cn;
            float h = ov*tanhf(cn);
            __half hq = __float2half(h);
            asm volatile("st.global.cg.u16 [%0], %1;"
                :: "l"(hout + (size_t)b*HPIT + (n0 >> 2) + jl),
                   "h"(*(const unsigned short*)&hq));
            if (last){
                int ci = b*HID + (n0 >> 2) + jl;
                out[ci] = h; out[BB*HID + ci] = cn;
            }
        }
        __syncthreads();

        // ---- distributed grid barrier ----
        if (tid == 0){
            __threadfence();
            asm volatile("st.global.release.gpu.s32 [%0], %1;"
                         :: "l"(g_flag + blockIdx.x), "r"(t + 1) : "memory");
        }
        if (tid < NCTA){
            int v;
            do {
                asm volatile("ld.global.acquire.gpu.s32 %0, [%1];"
                             : "=r"(v) : "l"(g_flag + tid));
            } while (v < t + 1);
        }
        __syncthreads();
    }
}

// ---------------- launch ----------------
extern "C" void kernel_launch(void* const* d_in, const int* in_sizes, int n_in,
                              void* d_out, int out_size){
    // dict order: x, Wii,Wfi,Wgi,Woi, Wih,Wfh,Wgh,Woh, bii,bih,bfi,bfh,bgi,bgh,boi,boh
    const float* x = nullptr;
    const float* w[8] = {nullptr}; const float* bp[8] = {nullptr};
    int nw = 0, nb = 0;
    for (int i = 0; i < n_in; i++){
        if (in_sizes[i] == ROWS*HID)      x = (const float*)d_in[i];
        else if (in_sizes[i] == HID*HID){ if (nw < 8) w[nw++] = (const float*)d_in[i]; }
        else if (in_sizes[i] == HID){     if (nb < 8) bp[nb++] = (const float*)d_in[i]; }
    }
    float* out = (float*)d_out;

    cudaFuncSetAttribute(k_xproj, cudaFuncAttributeMaxDynamicSharedMemorySize, XP_SMEM);
    cudaFuncSetAttribute(k_recur, cudaFuncAttributeMaxDynamicSharedMemorySize, RQ_SMEM);

    k_split_x<<<2048, 256>>>(x);
    k_prep_w<<<16384, 256>>>(w[0], w[1], w[2], w[3], w[4], w[5], w[6], w[7],
                             bp[0], bp[1], bp[2], bp[3], bp[4], bp[5], bp[6], bp[7]);
    k_init<<<256, 256>>>();
    dim3 gx(32, 256);
    k_xproj<<<gx, 256, XP_SMEM>>>();
    k_recur<<<NCTA, 256, RQ_SMEM>>>(out);
}